// round 9
// baseline (speedup 1.0000x reference)
#include <cuda_runtime.h>
#include <cstdint>

#define H    50
#define E    4
#define KPAD 64
#define BSZ  512
#define NTH  416

typedef unsigned long long u64;

__device__ __forceinline__ void fma2(u64 &d, u64 a, u64 b) {
    asm("fma.rn.f32x2 %0, %1, %2, %0;" : "+l"(d) : "l"(a), "l"(b));
}
__device__ __forceinline__ u64 padd(u64 a, u64 b) {
    u64 d; asm("add.rn.f32x2 %0, %1, %2;" : "=l"(d) : "l"(a), "l"(b)); return d;
}
__device__ __forceinline__ float lo32(u64 a){ return __uint_as_float((unsigned)a); }
__device__ __forceinline__ float hi32(u64 a){ return __uint_as_float((unsigned)(a >> 32)); }
__device__ __forceinline__ float hsum2(u64 a){ return lo32(a) + hi32(a); }
__device__ __forceinline__ u64 pk2(float lo, float hi) {
    return ((u64)__float_as_uint(hi) << 32) | (u64)__float_as_uint(lo);
}
__device__ __forceinline__ u64 shflx64(u64 v, int m) {
    unsigned lo = (unsigned)v, hi = (unsigned)(v >> 32);
    lo = __shfl_xor_sync(0xffffffffu, lo, m);
    hi = __shfl_xor_sync(0xffffffffu, hi, m);
    return ((u64)hi << 32) | lo;
}

// partial 4-row dot over this lane's 8 h-floats (2 LDS.128)
__device__ __forceinline__ void dot4(const float* __restrict__ hb, const u64 (&w)[4][4],
                                     u64 &ai, u64 &af, u64 &ag, u64 &ao) {
    const ulonglong2* hp = (const ulonglong2*)hb;
    ulonglong2 hA = hp[0];
    ulonglong2 hB = hp[1];
    fma2(ai, w[0][0], hA.x); fma2(af, w[1][0], hA.x); fma2(ag, w[2][0], hA.x); fma2(ao, w[3][0], hA.x);
    fma2(ai, w[0][1], hA.y); fma2(af, w[1][1], hA.y); fma2(ag, w[2][1], hA.y); fma2(ao, w[3][1], hA.y);
    fma2(ai, w[0][2], hB.x); fma2(af, w[1][2], hB.x); fma2(ag, w[2][2], hB.x); fma2(ao, w[3][2], hB.x);
    fma2(ai, w[0][3], hB.y); fma2(af, w[1][3], hB.y); fma2(ag, w[2][3], hB.y); fma2(ao, w[3][3], hB.y);
}

// reduce-scatter across the 8-lane group: P=(i,f), Q=(g,o) partials for elements A,B.
// Result: lane k<4 holds gate r(k) of element A; lanes 4-7 gate r(k&3) of element B,
// with role map r: 0->i, 1->g, 2->f, 3->o.
__device__ __forceinline__ float reduce_pair(u64 P0, u64 Q0, u64 P1, u64 Q1, int k) {
    u64 k0 = (k & 1) ? Q0 : P0;
    u64 g0 = (k & 1) ? P0 : Q0;
    k0 = padd(k0, shflx64(g0, 1));
    u64 k1 = (k & 1) ? Q1 : P1;
    u64 g1 = (k & 1) ? P1 : Q1;
    k1 = padd(k1, shflx64(g1, 1));
    float kf0 = (k & 2) ? hi32(k0) : lo32(k0);
    float gf0 = (k & 2) ? lo32(k0) : hi32(k0);
    float v0 = kf0 + __shfl_xor_sync(0xffffffffu, gf0, 2);
    float kf1 = (k & 2) ? hi32(k1) : lo32(k1);
    float gf1 = (k & 2) ? lo32(k1) : hi32(k1);
    float v1 = kf1 + __shfl_xor_sync(0xffffffffu, gf1, 2);
    float gv = (k & 4) ? v0 : v1;
    float rc = __shfl_xor_sync(0xffffffffu, gv, 4);
    return ((k & 4) ? v1 : v0) + rc;
}

// Distributed LSTM activation across the 4 role lanes (rl: 0=i,1=g,2=f,3=o).
// act = a*rcp(1+e^{s*pre}) + b : sigmoid (s=-1,a=1,b=0); tanh (s=2,a=-2,b=1).
// Returns h (valid at rl==3); updates c (valid at rl==2).
__device__ __forceinline__ float act_step(float pre, float sgn, float aco, float bco, float &c) {
    float Ev  = __expf(sgn * pre);
    float act = fmaf(aco, __fdividef(1.0f, 1.0f + Ev), bco);
    float oth = __shfl_xor_sync(0xffffffffu, act, 1);   // rl0<->rl1
    float pig = act * oth;                               // at rl1: sig(i)*tanh(g)
    float prc = __shfl_xor_sync(0xffffffffu, pig, 3);    // rl2 <- rl1
    c = fmaf(act, c, prc);                               // at rl2: sig(f)*c + sig(i)tanh(g)
    float E2  = __expf(2.0f * c);
    float tc  = fmaf(-2.0f, __fdividef(1.0f, 1.0f + E2), 1.0f);  // tanh(c) at rl2
    float tcr = __shfl_xor_sync(0xffffffffu, tc, 1);     // rl3 <- rl2
    return act * tcr;                                    // at rl3: sig(o)*tanh(c)
}

__global__ void __launch_bounds__(NTH, 1) sinelstm_kernel(
    const float* __restrict__ x,
    const float* __restrict__ W_ih1, const float* __restrict__ W_hh1,
    const float* __restrict__ b_ih1, const float* __restrict__ b_hh1,
    const float* __restrict__ W_ih2, const float* __restrict__ W_hh2,
    const float* __restrict__ b_ih2, const float* __restrict__ b_hh2,
    const float* __restrict__ W_lin, const float* __restrict__ b_lin,
    float* __restrict__ out, int T, int TP)
{
    __shared__ __align__(16) float h1s[2][E][KPAD];
    __shared__ __align__(16) float h2s[2][E][KPAD];
    __shared__ u64  part[13][2];
    __shared__ float outs_s[E];

    const int t    = threadIdx.x;
    const int base = blockIdx.x * E;
    const int u    = (t < 400) ? (t >> 3) : 49;   // threads 400-415 duplicate unit 49
    const int k    = t & 7;
    const int rl   = k & 3;                        // role lane: 0=i 1=g 2=f 3=o
    const int hf_  = k >> 2;                       // element offset within a pass
    const bool wr  = (rl == 3) && (t < 400);
    const int lane = t & 31, wrp = t >> 5;

    const float sgn = (rl == 1) ?  2.0f : -1.0f;
    const float aco = (rl == 1) ? -2.0f :  1.0f;
    const float bco = (rl == 1) ?  1.0f :  0.0f;
    const int  blk  = (rl == 0) ? 0 : (rl == 1) ? 2 : (rl == 2) ? 1 : 3;
    const int  arow = blk * H + u;

    // ---- register-resident weights: 4 gate rows of unit u, cols [8k, 8k+8) ----
    u64 w1[4][4], wa[4][4], wb[4][4];
    #pragma unroll
    for (int rr = 0; rr < 4; rr++) {
        const int row = rr * H + u;   // i,f,g,o row order
        #pragma unroll
        for (int p = 0; p < 4; p++) {
            const int col = k * 8 + 2 * p;
            float a0 = (col     < H) ? W_hh1[row * H + col]     : 0.f;
            float a1 = (col + 1 < H) ? W_hh1[row * H + col + 1] : 0.f;
            w1[rr][p] = pk2(a0, a1);
            float c0 = (col     < H) ? W_ih2[row * H + col]     : 0.f;
            float c1v= (col + 1 < H) ? W_ih2[row * H + col + 1] : 0.f;
            wa[rr][p] = pk2(c0, c1v);
            float d0 = (col     < H) ? W_hh2[row * H + col]     : 0.f;
            float d1 = (col + 1 < H) ? W_hh2[row * H + col + 1] : 0.f;
            wb[rr][p] = pk2(d0, d1);
        }
    }
    const float bias1  = b_ih1[arow] + b_hh1[arow];
    const float bias2  = b_ih2[arow] + b_hh2[arow];
    const float wx1    = W_ih1[arow];
    const float wlin_t = wr ? W_lin[u] : 0.f;
    const float blin   = b_lin[0];

    float c1[2] = {0.f, 0.f};
    float c2[2] = {0.f, 0.f};

    for (int i = t; i < 2 * E * KPAD; i += NTH) {
        ((float*)h1s)[i] = 0.f;
        ((float*)h2s)[i] = 0.f;
    }
    __syncthreads();

    int bufc = 0;

    // ---- phase lambdas (uniform across all 416 threads) ----
    auto phase1 = [&](float xv0, float xv1) {
        #pragma unroll
        for (int pa = 0; pa < 2; pa++) {
            const int eA = 2 * pa;
            u64 i0=0,f0=0,g0=0,o0=0, i1=0,f1=0,g1=0,o1=0;
            dot4(&h1s[bufc][eA][k * 8],     w1, i0, f0, g0, o0);
            dot4(&h1s[bufc][eA + 1][k * 8], w1, i1, f1, g1, o1);
            float v = reduce_pair(pk2(hsum2(i0), hsum2(f0)), pk2(hsum2(g0), hsum2(o0)),
                                  pk2(hsum2(i1), hsum2(f1)), pk2(hsum2(g1), hsum2(o1)), k);
            float pre = v + bias1 + wx1 * (pa ? xv1 : xv0);
            float h = act_step(pre, sgn, aco, bco, c1[pa]);
            if (wr) h1s[bufc ^ 1][eA + hf_][u] = h;
        }
    };
    auto phase2 = [&]() {
        float tm0 = 0.f, tm1 = 0.f;
        #pragma unroll
        for (int pa = 0; pa < 2; pa++) {
            const int eA = 2 * pa;
            u64 i0=0,f0=0,g0=0,o0=0, i1=0,f1=0,g1=0,o1=0;
            dot4(&h1s[bufc ^ 1][eA][k * 8],     wa, i0, f0, g0, o0);
            dot4(&h2s[bufc][eA][k * 8],         wb, i0, f0, g0, o0);
            dot4(&h1s[bufc ^ 1][eA + 1][k * 8], wa, i1, f1, g1, o1);
            dot4(&h2s[bufc][eA + 1][k * 8],     wb, i1, f1, g1, o1);
            float v = reduce_pair(pk2(hsum2(i0), hsum2(f0)), pk2(hsum2(g0), hsum2(o0)),
                                  pk2(hsum2(i1), hsum2(f1)), pk2(hsum2(g1), hsum2(o1)), k);
            float pre = v + bias2;
            float h = act_step(pre, sgn, aco, bco, c2[pa]);
            if (wr) h2s[bufc ^ 1][eA + hf_][u] = h;
            float tmv = wr ? (wlin_t * h) : 0.f;
            if (pa == 0) tm0 = tmv; else tm1 = tmv;
        }
        u64 tp = pk2(tm0, tm1);
        tp = padd(tp, shflx64(tp, 8));
        tp = padd(tp, shflx64(tp, 16));
        if (lane == 3)      part[wrp][0] = tp;   // (e0, e2)
        else if (lane == 7) part[wrp][1] = tp;   // (e1, e3)
    };
    auto finalize = [&](int step, bool seed) {
        if (t == 408 || t == 409) {
            const int idx = t - 408;
            u64 acc = part[0][idx];
            #pragma unroll
            for (int w = 1; w < 13; w++) acc = padd(acc, part[w][idx]);
            float oA = lo32(acc) + blin, oB = hi32(acc) + blin;
            out[(size_t)(base + idx) * TP + step]     = oA;
            out[(size_t)(base + idx + 2) * TP + step] = oB;
            if (seed) { outs_s[idx] = oA; outs_s[idx + 2] = oB; }
        }
    };

    // ================= main loop: 2 barriers/step, output finalize lagged =================
    for (int s = 0; s < T; s++) {
        float xv0 = __ldg(&x[(size_t)(base + hf_) * T + s]);
        float xv1 = __ldg(&x[(size_t)(base + 2 + hf_) * T + s]);
        if (s > 0) finalize(s - 1, false);
        phase1(xv0, xv1);
        __syncthreads();   // A: h1[next] visible
        phase2();
        __syncthreads();   // B: h2[next] + part visible
        bufc ^= 1;
    }

    // epilogue: finalize step T-1 and seed predict feedback
    finalize(T - 1, true);
    __syncthreads();

    // ================= predict loop: strict ordering (output feedback) =================
    for (int s = T; s < TP; s++) {
        float xv0 = outs_s[hf_];
        float xv1 = outs_s[2 + hf_];
        phase1(xv0, xv1);
        __syncthreads();
        phase2();
        __syncthreads();
        bufc ^= 1;
        finalize(s, true);
        __syncthreads();
    }
}

extern "C" void kernel_launch(void* const* d_in, const int* in_sizes, int n_in,
                              void* d_out, int out_size) {
    const float* x     = (const float*)d_in[0];
    const float* W_ih1 = (const float*)d_in[1];
    const float* W_hh1 = (const float*)d_in[2];
    const float* b_ih1 = (const float*)d_in[3];
    const float* b_hh1 = (const float*)d_in[4];
    const float* W_ih2 = (const float*)d_in[5];
    const float* W_hh2 = (const float*)d_in[6];
    const float* b_ih2 = (const float*)d_in[7];
    const float* b_hh2 = (const float*)d_in[8];
    const float* W_lin = (const float*)d_in[9];
    const float* b_lin = (const float*)d_in[10];

    int T  = in_sizes[0] / BSZ;      // 1024
    int TP = out_size   / BSZ;       // 1056

    sinelstm_kernel<<<BSZ / E, NTH>>>(
        x, W_ih1, W_hh1, b_ih1, b_hh1,
        W_ih2, W_hh2, b_ih2, b_hh2,
        W_lin, b_lin, (float*)d_out, T, TP);
}

// round 10
// speedup vs baseline: 1.9031x; 1.9031x over previous
#include <cuda_runtime.h>
#include <cstdint>

#define H    50
#define G4   200     // 4*H gate rows
#define E    4       // batch elements per block
#define BSZ  512
#define NTH  448
#define NCH  7       // ulonglong2 chunks per K-half
#define HPAD 56      // h padded to 14 chunks * 4 floats

typedef unsigned long long u64;

__device__ __forceinline__ void fma2(u64 &d, u64 a, u64 b) {
    asm("fma.rn.f32x2 %0, %1, %2, %0;" : "+l"(d) : "l"(a), "l"(b));
}
__device__ __forceinline__ float hsum2(u64 a) {
    return __uint_as_float((unsigned)(a & 0xffffffffu)) + __uint_as_float((unsigned)(a >> 32));
}
__device__ __forceinline__ u64 pk2(float lo, float hi) {
    return ((u64)__float_as_uint(hi) << 32) | (u64)__float_as_uint(lo);
}
__device__ __forceinline__ float sigf(float v) {
    return __fdividef(1.0f, 1.0f + __expf(-v));
}
__device__ __forceinline__ float tanhf_(float v) {
    return 1.0f - __fdividef(2.0f, 1.0f + __expf(2.0f * v));
}

__global__ void __launch_bounds__(NTH, 1) sinelstm_kernel(
    const float* __restrict__ x,
    const float* __restrict__ W_ih1, const float* __restrict__ W_hh1,
    const float* __restrict__ b_ih1, const float* __restrict__ b_hh1,
    const float* __restrict__ W_ih2, const float* __restrict__ W_hh2,
    const float* __restrict__ b_ih2, const float* __restrict__ b_hh2,
    const float* __restrict__ W_lin, const float* __restrict__ b_lin,
    float* __restrict__ out, int T, int TP)
{
    __shared__ __align__(16) float h1s[E][HPAD];     // current h1 (single buffer; phases alternate)
    __shared__ __align__(16) float h2s[E][HPAD];     // current h2
    __shared__ float g1[2][E][G4];                   // layer-1 gate partials, per K-half
    __shared__ float g2[2][E][G4];                   // layer-2 gate partials, per K-half
    __shared__ __align__(16) float obuf[E][52];      // per-unit output terms (padded)
    __shared__ float outs_s[E];                      // feedback for predict phase

    const int t    = threadIdx.x;
    const int base = blockIdx.x * E;
    const int pr   = t >> 1;          // gate row 0..223 (>=200 masked)
    const int hf   = t & 1;           // K-half
    const bool row_ok = (pr < G4);

    // ---- register-resident weights: row pr, K-half hf ----
    u64 w1p[2 * NCH], wa[2 * NCH], wb[2 * NCH];
    float bias1 = 0.f, bias2 = 0.f, wx1 = 0.f;
    {
        #pragma unroll
        for (int p = 0; p < 2 * NCH; p++) {
            int k = 2 * (hf * 2 * NCH + p);
            float a0 = (row_ok && k     < H) ? W_hh1[pr * H + k]     : 0.f;
            float a1 = (row_ok && k + 1 < H) ? W_hh1[pr * H + k + 1] : 0.f;
            w1p[p] = pk2(a0, a1);
            float c0 = (row_ok && k     < H) ? W_ih2[pr * H + k]     : 0.f;
            float c1v= (row_ok && k + 1 < H) ? W_ih2[pr * H + k + 1] : 0.f;
            wa[p] = pk2(c0, c1v);
            float d0 = (row_ok && k     < H) ? W_hh2[pr * H + k]     : 0.f;
            float d1 = (row_ok && k + 1 < H) ? W_hh2[pr * H + k + 1] : 0.f;
            wb[p] = pk2(d0, d1);
        }
        if (row_ok) {
            bias1 = b_ih1[pr] + b_hh1[pr];
            bias2 = b_ih2[pr] + b_hh2[pr];
            wx1   = W_ih1[pr];
        }
    }

    // ---- activation tasks: t<200 -> layer1 (e,u); 200<=t<400 -> layer2 (e,u) ----
    const bool l1t = (t < 200);
    const bool l2t = (t >= 200) && (t < 400);
    const int  ui  = t % 200;
    const int  ue  = ui / 50;
    const int  uu  = ui % 50;
    float cst = 0.f;                                  // c1 (l1t) or c2 (l2t)
    const float wlin_u = l2t ? __ldg(&W_lin[uu]) : 0.f;
    const float blin   = b_lin[0];

    // ---- finalizer threads (pad rows 220/221 — never row_ok STS targets... pr=220,221 masked) ----
    const bool fin = (t >= 440) && (t < 444);
    const int  fe  = t - 440;

    // init shared state
    for (int i = t; i < E * HPAD; i += NTH) { ((float*)h1s)[i] = 0.f; ((float*)h2s)[i] = 0.f; }
    for (int i = t; i < E * 52;   i += NTH) ((float*)obuf)[i] = 0.f;
    __syncthreads();

    // ---- helper lambdas ----
    auto dots_all = [&](int s) {   // region 1 of main loop: gates1(s) + gates2(s-1)
        #pragma unroll
        for (int e = 0; e < E; e++) {
            const ulonglong2* h1v = (const ulonglong2*)(&h1s[e][hf * 4 * NCH]);
            const ulonglong2* h2v = (const ulonglong2*)(&h2s[e][hf * 4 * NCH]);
            u64 a1 = 0ull, a2 = 0ull;
            #pragma unroll
            for (int q = 0; q < NCH; q++) {
                ulonglong2 hc = h1v[q];
                fma2(a1, w1p[2 * q],     hc.x);
                fma2(a1, w1p[2 * q + 1], hc.y);
                fma2(a2, wa[2 * q],      hc.x);
                fma2(a2, wa[2 * q + 1],  hc.y);
            }
            #pragma unroll
            for (int q = 0; q < NCH; q++) {
                ulonglong2 hc = h2v[q];
                fma2(a2, wb[2 * q],      hc.x);
                fma2(a2, wb[2 * q + 1],  hc.y);
            }
            float s1 = hsum2(a1);
            float s2 = hsum2(a2);
            if (hf == 0) {
                s1 += bias1 + wx1 * __ldg(&x[(size_t)(base + e) * T + s]);
                s2 += bias2;
            }
            g1[hf][e][pr] = s1;
            if (s > 0) g2[hf][e][pr] = s2;
        }
    };
    auto act1 = [&]() {
        float gi = g1[0][ue][uu]          + g1[1][ue][uu];
        float gf = g1[0][ue][H + uu]      + g1[1][ue][H + uu];
        float gg = g1[0][ue][2 * H + uu]  + g1[1][ue][2 * H + uu];
        float go = g1[0][ue][3 * H + uu]  + g1[1][ue][3 * H + uu];
        cst = sigf(gf) * cst + sigf(gi) * tanhf_(gg);
        h1s[ue][uu] = sigf(go) * tanhf_(cst);
    };
    auto act2 = [&]() {
        float gi = g2[0][ue][uu]          + g2[1][ue][uu];
        float gf = g2[0][ue][H + uu]      + g2[1][ue][H + uu];
        float gg = g2[0][ue][2 * H + uu]  + g2[1][ue][2 * H + uu];
        float go = g2[0][ue][3 * H + uu]  + g2[1][ue][3 * H + uu];
        cst = sigf(gf) * cst + sigf(gi) * tanhf_(gg);
        float h2 = sigf(go) * tanhf_(cst);
        h2s[ue][uu] = h2;
        obuf[ue][uu] = wlin_u * h2;
    };
    auto finalize_out = [&](int ostep, bool seed) {
        if (fin) {
            const float4* ob = (const float4*)obuf[fe];
            float a0 = 0.f, a1 = 0.f, a2 = 0.f, a3 = 0.f;
            #pragma unroll
            for (int q = 0; q < 13; q += 4) {
                float4 v0 = ob[q];     a0 += v0.x + v0.y + v0.z + v0.w;
                if (q + 1 < 13) { float4 v1 = ob[q + 1]; a1 += v1.x + v1.y + v1.z + v1.w; }
                if (q + 2 < 13) { float4 v2 = ob[q + 2]; a2 += v2.x + v2.y + v2.z + v2.w; }
                if (q + 3 < 13) { float4 v3 = ob[q + 3]; a3 += v3.x + v3.y + v3.z + v3.w; }
            }
            float o = (a0 + a1) + (a2 + a3) + blin;
            out[(size_t)(base + fe) * TP + ostep] = o;
            if (seed) outs_s[fe] = o;
        }
    };

    // ================= main loop: 2 barriers/step =================
    // iter s: R1 = dots for gates1(s) & gates2(s-1), finalize out(s-2)
    //         R2 = act1 -> h1(s);  act2 -> h2(s-1), obuf(s-1)
    for (int s = 0; s < T; s++) {
        if (row_ok) dots_all(s);
        else if (s >= 2) finalize_out(s - 2, false);
        __syncthreads();   // A
        if (l1t) act1();
        else if (l2t && s > 0) act2();
        __syncthreads();   // B
    }

    // ---- epilogue: out(T-2), then gates2(T-1)/act2, then out(T-1)+seed ----
    if (row_ok) {   // gates2(T-1) = W_ih2*h1(T-1) + W_hh2*h2(T-2)
        #pragma unroll
        for (int e = 0; e < E; e++) {
            const ulonglong2* h1v = (const ulonglong2*)(&h1s[e][hf * 4 * NCH]);
            const ulonglong2* h2v = (const ulonglong2*)(&h2s[e][hf * 4 * NCH]);
            u64 a2 = 0ull;
            #pragma unroll
            for (int q = 0; q < NCH; q++) {
                ulonglong2 ha = h1v[q];
                ulonglong2 hb = h2v[q];
                fma2(a2, wa[2 * q],     ha.x);
                fma2(a2, wa[2 * q + 1], ha.y);
                fma2(a2, wb[2 * q],     hb.x);
                fma2(a2, wb[2 * q + 1], hb.y);
            }
            float s2 = hsum2(a2);
            if (hf == 0) s2 += bias2;
            g2[hf][e][pr] = s2;
        }
    } else {
        finalize_out(T - 2, false);
    }
    __syncthreads();
    if (l2t) act2();
    __syncthreads();
    finalize_out(T - 1, true);
    __syncthreads();

    // ================= predict loop: strict ordering =================
    for (int s = T; s < TP; s++) {
        if (row_ok) {   // gates1(s), x = previous output
            #pragma unroll
            for (int e = 0; e < E; e++) {
                const ulonglong2* h1v = (const ulonglong2*)(&h1s[e][hf * 4 * NCH]);
                u64 a1 = 0ull;
                #pragma unroll
                for (int q = 0; q < NCH; q++) {
                    ulonglong2 hc = h1v[q];
                    fma2(a1, w1p[2 * q],     hc.x);
                    fma2(a1, w1p[2 * q + 1], hc.y);
                }
                float s1 = hsum2(a1);
                if (hf == 0) s1 += bias1 + wx1 * outs_s[e];
                g1[hf][e][pr] = s1;
            }
        }
        __syncthreads();
        if (l1t) act1();
        __syncthreads();
        if (row_ok) {   // gates2(s)
            #pragma unroll
            for (int e = 0; e < E; e++) {
                const ulonglong2* h1v = (const ulonglong2*)(&h1s[e][hf * 4 * NCH]);
                const ulonglong2* h2v = (const ulonglong2*)(&h2s[e][hf * 4 * NCH]);
                u64 a2 = 0ull;
                #pragma unroll
                for (int q = 0; q < NCH; q++) {
                    ulonglong2 ha = h1v[q];
                    ulonglong2 hb = h2v[q];
                    fma2(a2, wa[2 * q],     ha.x);
                    fma2(a2, wa[2 * q + 1], ha.y);
                    fma2(a2, wb[2 * q],     hb.x);
                    fma2(a2, wb[2 * q + 1], hb.y);
                }
                float s2 = hsum2(a2);
                if (hf == 0) s2 += bias2;
                g2[hf][e][pr] = s2;
            }
        }
        __syncthreads();
        if (l2t) act2();
        __syncthreads();
        finalize_out(s, true);
        __syncthreads();
    }
}

extern "C" void kernel_launch(void* const* d_in, const int* in_sizes, int n_in,
                              void* d_out, int out_size) {
    const float* x     = (const float*)d_in[0];
    const float* W_ih1 = (const float*)d_in[1];
    const float* W_hh1 = (const float*)d_in[2];
    const float* b_ih1 = (const float*)d_in[3];
    const float* b_hh1 = (const float*)d_in[4];
    const float* W_ih2 = (const float*)d_in[5];
    const float* W_hh2 = (const float*)d_in[6];
    const float* b_ih2 = (const float*)d_in[7];
    const float* b_hh2 = (const float*)d_in[8];
    const float* W_lin = (const float*)d_in[9];
    const float* b_lin = (const float*)d_in[10];

    int T  = in_sizes[0] / BSZ;      // 1024
    int TP = out_size   / BSZ;       // 1056

    sinelstm_kernel<<<BSZ / E, NTH>>>(
        x, W_ih1, W_hh1, b_ih1, b_hh1,
        W_ih2, W_hh2, b_ih2, b_hh2,
        W_lin, b_lin, (float*)d_out, T, TP);
}